// round 3
// baseline (speedup 1.0000x reference)
#include <cuda_runtime.h>
#include <math.h>

#define BB 4
#define TT 2048
#define CC 1024
#define NH 16
#define HD 64
#define ATT_SCALE 0.125f   // 1/sqrt(64)

// Scratch buffers (no cudaMalloc allowed)
__device__ float g_qkv[BB * TT * 3 * CC];   // 96 MB: (B, T, 3C)  [Q | K | V] per token
__device__ float g_wv [BB * TT * CC];       // 32 MB: (B, T, C)

// ---------------------------------------------------------------------------
// GEMM: out[M,N] = A[M,K] @ W[K,N] + bias[N]
// Tiles: BM=128, BN=64, BK=16. 256 threads, each computes 8x4.
// ---------------------------------------------------------------------------
__global__ __launch_bounds__(256)
void gemm_bias_kernel(const float* __restrict__ A, const float* __restrict__ W,
                      const float* __restrict__ bias, float* __restrict__ out,
                      int M, int N, int K)
{
    __shared__ float As[16][132];   // [BK][BM+4] transposed, padded
    __shared__ float Bs[16][64];    // [BK][BN]

    const int tid = threadIdx.x;
    const int tx = tid & 15;        // 0..15 -> col group
    const int ty = tid >> 4;        // 0..15 -> row group
    const int row0 = blockIdx.y * 128;
    const int col0 = blockIdx.x * 64;

    float acc[8][4];
    #pragma unroll
    for (int i = 0; i < 8; i++)
        #pragma unroll
        for (int j = 0; j < 4; j++) acc[i][j] = 0.0f;

    const float* Aptr = A + (size_t)row0 * K;

    for (int k0 = 0; k0 < K; k0 += 16) {
        // Load A tile (128x16) -> As transposed [16][128+pad]
        #pragma unroll
        for (int l = 0; l < 2; l++) {
            int i = tid + l * 256;          // 0..511
            int r = i >> 2;                 // 0..127
            int c = (i & 3) << 2;           // 0,4,8,12
            float4 v = *(const float4*)(Aptr + (size_t)r * K + k0 + c);
            As[c + 0][r] = v.x;
            As[c + 1][r] = v.y;
            As[c + 2][r] = v.z;
            As[c + 3][r] = v.w;
        }
        // Load B tile (16x64)
        {
            int r = tid >> 4;               // 0..15
            int c = (tid & 15) << 2;        // 0..60
            *(float4*)&Bs[r][c] = *(const float4*)(W + (size_t)(k0 + r) * N + col0 + c);
        }
        __syncthreads();

        #pragma unroll
        for (int k = 0; k < 16; k++) {
            float a[8], bv[4];
            float4 a0 = *(const float4*)&As[k][ty * 8];
            float4 a1 = *(const float4*)&As[k][ty * 8 + 4];
            a[0] = a0.x; a[1] = a0.y; a[2] = a0.z; a[3] = a0.w;
            a[4] = a1.x; a[5] = a1.y; a[6] = a1.z; a[7] = a1.w;
            float4 b0 = *(const float4*)&Bs[k][tx * 4];
            bv[0] = b0.x; bv[1] = b0.y; bv[2] = b0.z; bv[3] = b0.w;
            #pragma unroll
            for (int i = 0; i < 8; i++)
                #pragma unroll
                for (int j = 0; j < 4; j++)
                    acc[i][j] = fmaf(a[i], bv[j], acc[i][j]);
        }
        __syncthreads();
    }

    #pragma unroll
    for (int i = 0; i < 8; i++) {
        float4 v;
        v.x = acc[i][0] + bias[col0 + tx * 4 + 0];
        v.y = acc[i][1] + bias[col0 + tx * 4 + 1];
        v.z = acc[i][2] + bias[col0 + tx * 4 + 2];
        v.w = acc[i][3] + bias[col0 + tx * 4 + 3];
        *(float4*)(out + (size_t)(row0 + ty * 8 + i) * N + col0 + tx * 4) = v;
    }
}

// ---------------------------------------------------------------------------
// Flash attention (causal + additive padding mask), fp32.
// Grid: (T/128, B*NH). Block: 128 threads, one query row per thread.
// K/V tiles of 64 keys staged in shared memory; all SMEM reads broadcast.
// ---------------------------------------------------------------------------
__global__ __launch_bounds__(128)
void attn_kernel(const float* __restrict__ qkv, const float* __restrict__ amask,
                 float* __restrict__ wv)
{
    __shared__ float Ks[64][HD];
    __shared__ float Vs[64][HD];
    __shared__ float Ps[64];     // additive pad per key

    const int tid = threadIdx.x;
    const int bh  = blockIdx.y;
    const int b   = bh / NH;
    const int h   = bh % NH;
    const int q   = blockIdx.x * 128 + tid;

    const float* base = qkv + (size_t)b * TT * 3 * CC;
    const float* qptr = base + (size_t)q * 3 * CC + h * HD;

    float4 qreg[HD / 4];
    #pragma unroll
    for (int i = 0; i < HD / 4; i++) qreg[i] = *(const float4*)(qptr + 4 * i);

    float o[HD];
    #pragma unroll
    for (int d = 0; d < HD; d++) o[d] = 0.0f;
    float m = -INFINITY;
    float l = 0.0f;

    const int kmax = blockIdx.x * 128 + 127;   // last query row in this block

    for (int k0 = 0; k0 <= kmax; k0 += 64) {
        __syncthreads();
        // Stage 64 K rows + 64 V rows (each 64 floats) = 1024 float4 per tensor
        #pragma unroll
        for (int l2 = 0; l2 < 8; l2++) {
            int i = tid + l2 * 128;           // 0..1023
            int r = i >> 4;                   // 0..63
            int c = (i & 15) << 2;            // 0..60
            const float* kp = base + (size_t)(k0 + r) * 3 * CC + CC + h * HD + c;
            *(float4*)&Ks[r][c] = *(const float4*)kp;
            *(float4*)&Vs[r][c] = *(const float4*)(kp + CC);
        }
        if (tid < 64)
            Ps[tid] = (1.0f - amask[b * TT + k0 + tid]) * (-3.402823466e38f);
        __syncthreads();

        if (k0 > q) continue;   // uniform iteration count per block; syncs stay aligned

        float p[64];
        float mt = m;
        #pragma unroll
        for (int j = 0; j < 64; j++) {
            int kk = k0 + j;
            float s;
            if (kk > q) {
                s = -INFINITY;
            } else {
                float acc = 0.0f;
                #pragma unroll
                for (int d4 = 0; d4 < HD / 4; d4++) {
                    float4 kv = *(const float4*)&Ks[j][d4 * 4];
                    acc = fmaf(qreg[d4].x, kv.x, acc);
                    acc = fmaf(qreg[d4].y, kv.y, acc);
                    acc = fmaf(qreg[d4].z, kv.z, acc);
                    acc = fmaf(qreg[d4].w, kv.w, acc);
                }
                s = acc * ATT_SCALE + Ps[j];
            }
            p[j] = s;
            mt = fmaxf(mt, s);
        }

        float alpha = __expf(m - mt);
        m = mt;
        l *= alpha;
        #pragma unroll
        for (int d = 0; d < HD; d++) o[d] *= alpha;

        #pragma unroll
        for (int j = 0; j < 64; j++) {
            float pe = __expf(p[j] - mt);
            l += pe;
            #pragma unroll
            for (int d = 0; d < HD; d++)
                o[d] = fmaf(pe, Vs[j][d], o[d]);
        }
    }

    const float inv = 1.0f / l;
    float* op = wv + ((size_t)b * TT + q) * CC + h * HD;
    #pragma unroll
    for (int i = 0; i < HD / 4; i++) {
        float4 v;
        v.x = o[4 * i + 0] * inv;
        v.y = o[4 * i + 1] * inv;
        v.z = o[4 * i + 2] * inv;
        v.w = o[4 * i + 3] * inv;
        *(float4*)(op + 4 * i) = v;
    }
}

// ---------------------------------------------------------------------------
extern "C" void kernel_launch(void* const* d_in, const int* in_sizes, int n_in,
                              void* d_out, int out_size)
{
    (void)in_sizes; (void)n_in; (void)out_size;
    const float* x      = (const float*)d_in[0];
    const float* amask  = (const float*)d_in[1];
    const float* W_qkv  = (const float*)d_in[2];
    const float* b_qkv  = (const float*)d_in[3];
    const float* W_out  = (const float*)d_in[4];
    const float* b_out  = (const float*)d_in[5];
    float* out = (float*)d_out;

    float* qkv_ptr = nullptr;
    float* wv_ptr  = nullptr;
    cudaGetSymbolAddress((void**)&qkv_ptr, g_qkv);
    cudaGetSymbolAddress((void**)&wv_ptr,  g_wv);

    // 1) QKV projection: (8192 x 1024) @ (1024 x 3072) + b
    {
        dim3 grid(3 * CC / 64, (BB * TT) / 128);
        gemm_bias_kernel<<<grid, 256>>>(x, W_qkv, b_qkv, qkv_ptr,
                                        BB * TT, 3 * CC, CC);
    }
    // 2) Causal masked attention per (b, h)
    {
        dim3 grid(TT / 128, BB * NH);
        attn_kernel<<<grid, 128>>>(qkv_ptr, amask, wv_ptr);
    }
    // 3) Output projection: (8192 x 1024) @ (1024 x 1024) + b
    {
        dim3 grid(CC / 64, (BB * TT) / 128);
        gemm_bias_kernel<<<grid, 256>>>(wv_ptr, W_out, b_out, out,
                                        BB * TT, CC, CC);
    }
}

// round 5
// speedup vs baseline: 1.3213x; 1.3213x over previous
#include <cuda_runtime.h>
#include <math.h>
#include <stdint.h>

#define BB 4
#define TT 2048
#define CC 1024
#define NH 16
#define HD 64
#define ATT_SCALE 0.125f   // 1/sqrt(64)

// Scratch buffers (no cudaMalloc allowed)
__device__ float g_qkv[BB * TT * 3 * CC];   // 96 MB: (B, T, 3C)
__device__ float g_wv [BB * TT * CC];       // 32 MB: (B, T, C)

// ---------------------------------------------------------------------------
// PTX helpers
// ---------------------------------------------------------------------------
__device__ __forceinline__ uint32_t smem_u32(const void* p) {
    return (uint32_t)__cvta_generic_to_shared(p);
}
__device__ __forceinline__ void cp_async16(uint32_t dst, const void* src) {
    asm volatile("cp.async.cg.shared.global [%0], [%1], 16;\n" :: "r"(dst), "l"(src));
}
__device__ __forceinline__ void cp_commit() {
    asm volatile("cp.async.commit_group;\n");
}
template<int N>
__device__ __forceinline__ void cp_wait() {
    asm volatile("cp.async.wait_group %0;\n" :: "n"(N));
}
// Round-to-nearest fp32 -> tf32 (unbiased; raw truncation would bias dot
// products by ~2^-11 which is at the 1e-3 rel_err threshold).
__device__ __forceinline__ uint32_t f2tf32(float x) {
    uint32_t r;
    asm("cvt.rna.tf32.f32 %0, %1;\n" : "=r"(r) : "f"(x));
    return r;
}
__device__ __forceinline__ void mma_tf32(float d[4], const uint32_t a[4], const uint32_t b[2]) {
    asm volatile(
        "mma.sync.aligned.m16n8k8.row.col.f32.tf32.tf32.f32 "
        "{%0,%1,%2,%3}, {%4,%5,%6,%7}, {%8,%9}, {%0,%1,%2,%3};\n"
        : "+f"(d[0]), "+f"(d[1]), "+f"(d[2]), "+f"(d[3])
        : "r"(a[0]), "r"(a[1]), "r"(a[2]), "r"(a[3]), "r"(b[0]), "r"(b[1]));
}

// ---------------------------------------------------------------------------
// TF32 tensor-core GEMM: out[M,N] = A[M,K] @ W[K,N] + bias[N]
// Block tile 128x128x16, 8 warps (2m x 4n), warp tile 64x32.
// A smem [128][20]  (stride 20 mod 32 = 20 -> conflict-free frag loads)
// B smem [16][136]  (stride 136 mod 32 = 8 -> conflict-free frag loads)
// cp.async double-buffered.
// ---------------------------------------------------------------------------
#define ASTRIDE 20
#define BSTRIDE 136

__global__ __launch_bounds__(256)
void gemm_tf32_kernel(const float* __restrict__ A, const float* __restrict__ W,
                      const float* __restrict__ bias, float* __restrict__ out,
                      int M, int N, int K)
{
    __shared__ float As[2][128 * ASTRIDE];
    __shared__ float Bs[2][16 * BSTRIDE];

    const int tid  = threadIdx.x;
    const int warp = tid >> 5;
    const int lane = tid & 31;
    const int wm   = warp >> 2;      // 0..1
    const int wn   = warp & 3;       // 0..3
    const int g    = lane >> 2;      // 0..7
    const int tg   = lane & 3;       // 0..3

    const int row0 = blockIdx.y * 128;
    const int col0 = blockIdx.x * 128;

    float acc[4][4][4];
    #pragma unroll
    for (int im = 0; im < 4; im++)
        #pragma unroll
        for (int in = 0; in < 4; in++)
            #pragma unroll
            for (int r = 0; r < 4; r++) acc[im][in][r] = 0.0f;

    // Per-thread load coordinates (2 float4 per tensor per stage)
    //  A: i in [0,512): m = i>>2, kq = (i&3)*4
    //  B: i in [0,512): k = i>>5, nq = (i&31)*4
    const int am0 = tid >> 2,        akq = (tid & 3) * 4;
    const int am1 = (tid + 256) >> 2;               // akq identical
    const int bk0 = tid >> 5,        bnq = (tid & 31) * 4;
    const int bk1 = (tid + 256) >> 5;

    const float* Abase = A + (size_t)row0 * K;
    const float* Wbase = W + col0;

    auto load_stage = [&](int st, int k0) {
        uint32_t adst = smem_u32(&As[st][0]);
        uint32_t bdst = smem_u32(&Bs[st][0]);
        cp_async16(adst + (am0 * ASTRIDE + akq) * 4, Abase + (size_t)am0 * K + k0 + akq);
        cp_async16(adst + (am1 * ASTRIDE + akq) * 4, Abase + (size_t)am1 * K + k0 + akq);
        cp_async16(bdst + (bk0 * BSTRIDE + bnq) * 4, Wbase + (size_t)(k0 + bk0) * N + bnq);
        cp_async16(bdst + (bk1 * BSTRIDE + bnq) * 4, Wbase + (size_t)(k0 + bk1) * N + bnq);
    };

    const int nk = K / 16;
    load_stage(0, 0);
    cp_commit();

    for (int kt = 0; kt < nk; kt++) {
        const int st = kt & 1;
        if (kt + 1 < nk) {
            load_stage(st ^ 1, (kt + 1) * 16);
            cp_commit();
            cp_wait<1>();
        } else {
            cp_wait<0>();
        }
        __syncthreads();

        const float* as  = As[st];
        const float* bsm = Bs[st];
        #pragma unroll
        for (int ks = 0; ks < 16; ks += 8) {
            uint32_t af[4][4];
            uint32_t bf[4][2];
            #pragma unroll
            for (int im = 0; im < 4; im++) {
                const int m0 = wm * 64 + im * 16 + g;
                af[im][0] = f2tf32(as[(size_t)m0       * ASTRIDE + ks + tg]);
                af[im][1] = f2tf32(as[(size_t)(m0 + 8) * ASTRIDE + ks + tg]);
                af[im][2] = f2tf32(as[(size_t)m0       * ASTRIDE + ks + tg + 4]);
                af[im][3] = f2tf32(as[(size_t)(m0 + 8) * ASTRIDE + ks + tg + 4]);
            }
            #pragma unroll
            for (int in = 0; in < 4; in++) {
                const int n0 = wn * 32 + in * 8 + g;
                bf[in][0] = f2tf32(bsm[(size_t)(ks + tg)     * BSTRIDE + n0]);
                bf[in][1] = f2tf32(bsm[(size_t)(ks + tg + 4) * BSTRIDE + n0]);
            }
            #pragma unroll
            for (int im = 0; im < 4; im++)
                #pragma unroll
                for (int in = 0; in < 4; in++)
                    mma_tf32(acc[im][in], af[im], bf[in]);
        }
        __syncthreads();
    }

    // Epilogue: bias add + store. c0,c1 -> (row g,   col 2tg, 2tg+1)
    //                            c2,c3 -> (row g+8, same cols)
    #pragma unroll
    for (int in = 0; in < 4; in++) {
        const int col = col0 + wn * 32 + in * 8 + 2 * tg;
        const float2 bv = *(const float2*)(bias + col);
        #pragma unroll
        for (int im = 0; im < 4; im++) {
            const int r = row0 + wm * 64 + im * 16 + g;
            float2 v0 = { acc[im][in][0] + bv.x, acc[im][in][1] + bv.y };
            float2 v1 = { acc[im][in][2] + bv.x, acc[im][in][3] + bv.y };
            *(float2*)(out + (size_t)r * N + col)       = v0;
            *(float2*)(out + (size_t)(r + 8) * N + col) = v1;
        }
    }
}

// ---------------------------------------------------------------------------
// Flash attention (causal + additive padding mask), fp32. Unchanged.
// ---------------------------------------------------------------------------
__global__ __launch_bounds__(128)
void attn_kernel(const float* __restrict__ qkv, const float* __restrict__ amask,
                 float* __restrict__ wv)
{
    __shared__ float Ks[64][HD];
    __shared__ float Vs[64][HD];
    __shared__ float Ps[64];

    const int tid = threadIdx.x;
    const int bh  = blockIdx.y;
    const int b   = bh / NH;
    const int h   = bh % NH;
    const int q   = blockIdx.x * 128 + tid;

    const float* base = qkv + (size_t)b * TT * 3 * CC;
    const float* qptr = base + (size_t)q * 3 * CC + h * HD;

    float4 qreg[HD / 4];
    #pragma unroll
    for (int i = 0; i < HD / 4; i++) qreg[i] = *(const float4*)(qptr + 4 * i);

    float o[HD];
    #pragma unroll
    for (int d = 0; d < HD; d++) o[d] = 0.0f;
    float m = -INFINITY;
    float l = 0.0f;

    const int kmax = blockIdx.x * 128 + 127;

    for (int k0 = 0; k0 <= kmax; k0 += 64) {
        __syncthreads();
        #pragma unroll
        for (int l2 = 0; l2 < 8; l2++) {
            int i = tid + l2 * 128;
            int r = i >> 4;
            int c = (i & 15) << 2;
            const float* kp = base + (size_t)(k0 + r) * 3 * CC + CC + h * HD + c;
            *(float4*)&Ks[r][c] = *(const float4*)kp;
            *(float4*)&Vs[r][c] = *(const float4*)(kp + CC);
        }
        if (tid < 64)
            Ps[tid] = (1.0f - amask[b * TT + k0 + tid]) * (-3.402823466e38f);
        __syncthreads();

        if (k0 > q) continue;

        float p[64];
        float mt = m;
        #pragma unroll
        for (int j = 0; j < 64; j++) {
            int kk = k0 + j;
            float s;
            if (kk > q) {
                s = -INFINITY;
            } else {
                float acc = 0.0f;
                #pragma unroll
                for (int d4 = 0; d4 < HD / 4; d4++) {
                    float4 kv = *(const float4*)&Ks[j][d4 * 4];
                    acc = fmaf(qreg[d4].x, kv.x, acc);
                    acc = fmaf(qreg[d4].y, kv.y, acc);
                    acc = fmaf(qreg[d4].z, kv.z, acc);
                    acc = fmaf(qreg[d4].w, kv.w, acc);
                }
                s = acc * ATT_SCALE + Ps[j];
            }
            p[j] = s;
            mt = fmaxf(mt, s);
        }

        float alpha = __expf(m - mt);
        m = mt;
        l *= alpha;
        #pragma unroll
        for (int d = 0; d < HD; d++) o[d] *= alpha;

        #pragma unroll
        for (int j = 0; j < 64; j++) {
            float pe = __expf(p[j] - mt);
            l += pe;
            #pragma unroll
            for (int d = 0; d < HD; d++)
                o[d] = fmaf(pe, Vs[j][d], o[d]);
        }
    }

    const float inv = 1.0f / l;
    float* op = wv + ((size_t)b * TT + q) * CC + h * HD;
    #pragma unroll
    for (int i = 0; i < HD / 4; i++) {
        float4 v;
        v.x = o[4 * i + 0] * inv;
        v.y = o[4 * i + 1] * inv;
        v.z = o[4 * i + 2] * inv;
        v.w = o[4 * i + 3] * inv;
        *(float4*)(op + 4 * i) = v;
    }
}

// ---------------------------------------------------------------------------
extern "C" void kernel_launch(void* const* d_in, const int* in_sizes, int n_in,
                              void* d_out, int out_size)
{
    (void)in_sizes; (void)n_in; (void)out_size;
    const float* x      = (const float*)d_in[0];
    const float* amask  = (const float*)d_in[1];
    const float* W_qkv  = (const float*)d_in[2];
    const float* b_qkv  = (const float*)d_in[3];
    const float* W_out  = (const float*)d_in[4];
    const float* b_out  = (const float*)d_in[5];
    float* out = (float*)d_out;

    float* qkv_ptr = nullptr;
    float* wv_ptr  = nullptr;
    cudaGetSymbolAddress((void**)&qkv_ptr, g_qkv);
    cudaGetSymbolAddress((void**)&wv_ptr,  g_wv);

    // 1) QKV projection: (8192 x 1024) @ (1024 x 3072) + b
    {
        dim3 grid(3 * CC / 128, (BB * TT) / 128);
        gemm_tf32_kernel<<<grid, 256>>>(x, W_qkv, b_qkv, qkv_ptr,
                                        BB * TT, 3 * CC, CC);
    }
    // 2) Causal masked attention per (b, h)
    {
        dim3 grid(TT / 128, BB * NH);
        attn_kernel<<<grid, 128>>>(qkv_ptr, amask, wv_ptr);
    }
    // 3) Output projection: (8192 x 1024) @ (1024 x 1024) + b
    {
        dim3 grid(CC / 128, (BB * TT) / 128);
        gemm_tf32_kernel<<<grid, 256>>>(wv_ptr, W_out, b_out, out,
                                        BB * TT, CC, CC);
    }
}

// round 9
// speedup vs baseline: 4.4383x; 3.3591x over previous
#include <cuda_runtime.h>
#include <math.h>
#include <stdint.h>

#define BB 4
#define TT 2048
#define CC 1024
#define NH 16
#define HD 64
#define ATT_SCALE 0.125f   // 1/sqrt(64)

// Scratch buffers (no cudaMalloc allowed)
__device__ float g_qkv[BB * TT * 3 * CC];   // 96 MB: (B, T, 3C)
__device__ float g_wv [BB * TT * CC];       // 32 MB: (B, T, C)

// ---------------------------------------------------------------------------
// PTX helpers
// ---------------------------------------------------------------------------
__device__ __forceinline__ uint32_t smem_u32(const void* p) {
    return (uint32_t)__cvta_generic_to_shared(p);
}
__device__ __forceinline__ void cp_async16(uint32_t dst, const void* src) {
    asm volatile("cp.async.cg.shared.global [%0], [%1], 16;\n" :: "r"(dst), "l"(src));
}
__device__ __forceinline__ void cp_commit() {
    asm volatile("cp.async.commit_group;\n");
}
template<int N>
__device__ __forceinline__ void cp_wait() {
    asm volatile("cp.async.wait_group %0;\n" :: "n"(N));
}
// Round-to-nearest fp32 -> tf32 (unbiased)
__device__ __forceinline__ uint32_t f2tf32(float x) {
    uint32_t r;
    asm("cvt.rna.tf32.f32 %0, %1;\n" : "=r"(r) : "f"(x));
    return r;
}
__device__ __forceinline__ void mma_tf32(float d[4], const uint32_t a[4], const uint32_t b[2]) {
    asm volatile(
        "mma.sync.aligned.m16n8k8.row.col.f32.tf32.tf32.f32 "
        "{%0,%1,%2,%3}, {%4,%5,%6,%7}, {%8,%9}, {%0,%1,%2,%3};\n"
        : "+f"(d[0]), "+f"(d[1]), "+f"(d[2]), "+f"(d[3])
        : "r"(a[0]), "r"(a[1]), "r"(a[2]), "r"(a[3]), "r"(b[0]), "r"(b[1]));
}

// ---------------------------------------------------------------------------
// TF32 tensor-core GEMM: out[M,N] = A[M,K] @ W[K,N] + bias[N]
// Block tile 128x128x16, 8 warps (2m x 4n), warp tile 64x32, cp.async 2-stage.
// ---------------------------------------------------------------------------
#define ASTRIDE 20
#define BSTRIDE 136

__global__ __launch_bounds__(256)
void gemm_tf32_kernel(const float* __restrict__ A, const float* __restrict__ W,
                      const float* __restrict__ bias, float* __restrict__ out,
                      int M, int N, int K)
{
    __shared__ float As[2][128 * ASTRIDE];
    __shared__ float Bs[2][16 * BSTRIDE];

    const int tid  = threadIdx.x;
    const int warp = tid >> 5;
    const int lane = tid & 31;
    const int wm   = warp >> 2;
    const int wn   = warp & 3;
    const int g    = lane >> 2;
    const int tg   = lane & 3;

    const int row0 = blockIdx.y * 128;
    const int col0 = blockIdx.x * 128;

    float acc[4][4][4];
    #pragma unroll
    for (int im = 0; im < 4; im++)
        #pragma unroll
        for (int in = 0; in < 4; in++)
            #pragma unroll
            for (int r = 0; r < 4; r++) acc[im][in][r] = 0.0f;

    const int am0 = tid >> 2,        akq = (tid & 3) * 4;
    const int am1 = (tid + 256) >> 2;
    const int bk0 = tid >> 5,        bnq = (tid & 31) * 4;
    const int bk1 = (tid + 256) >> 5;

    const float* Abase = A + (size_t)row0 * K;
    const float* Wbase = W + col0;

    auto load_stage = [&](int st, int k0) {
        uint32_t adst = smem_u32(&As[st][0]);
        uint32_t bdst = smem_u32(&Bs[st][0]);
        cp_async16(adst + (am0 * ASTRIDE + akq) * 4, Abase + (size_t)am0 * K + k0 + akq);
        cp_async16(adst + (am1 * ASTRIDE + akq) * 4, Abase + (size_t)am1 * K + k0 + akq);
        cp_async16(bdst + (bk0 * BSTRIDE + bnq) * 4, Wbase + (size_t)(k0 + bk0) * N + bnq);
        cp_async16(bdst + (bk1 * BSTRIDE + bnq) * 4, Wbase + (size_t)(k0 + bk1) * N + bnq);
    };

    const int nk = K / 16;
    load_stage(0, 0);
    cp_commit();

    for (int kt = 0; kt < nk; kt++) {
        const int st = kt & 1;
        if (kt + 1 < nk) {
            load_stage(st ^ 1, (kt + 1) * 16);
            cp_commit();
            cp_wait<1>();
        } else {
            cp_wait<0>();
        }
        __syncthreads();

        const float* as  = As[st];
        const float* bsm = Bs[st];
        #pragma unroll
        for (int ks = 0; ks < 16; ks += 8) {
            uint32_t af[4][4];
            uint32_t bf[4][2];
            #pragma unroll
            for (int im = 0; im < 4; im++) {
                const int m0 = wm * 64 + im * 16 + g;
                af[im][0] = f2tf32(as[(size_t)m0       * ASTRIDE + ks + tg]);
                af[im][1] = f2tf32(as[(size_t)(m0 + 8) * ASTRIDE + ks + tg]);
                af[im][2] = f2tf32(as[(size_t)m0       * ASTRIDE + ks + tg + 4]);
                af[im][3] = f2tf32(as[(size_t)(m0 + 8) * ASTRIDE + ks + tg + 4]);
            }
            #pragma unroll
            for (int in = 0; in < 4; in++) {
                const int n0 = wn * 32 + in * 8 + g;
                bf[in][0] = f2tf32(bsm[(size_t)(ks + tg)     * BSTRIDE + n0]);
                bf[in][1] = f2tf32(bsm[(size_t)(ks + tg + 4) * BSTRIDE + n0]);
            }
            #pragma unroll
            for (int im = 0; im < 4; im++)
                #pragma unroll
                for (int in = 0; in < 4; in++)
                    mma_tf32(acc[im][in], af[im], bf[in]);
        }
        __syncthreads();
    }

    #pragma unroll
    for (int in = 0; in < 4; in++) {
        const int col = col0 + wn * 32 + in * 8 + 2 * tg;
        const float2 bv = *(const float2*)(bias + col);
        #pragma unroll
        for (int im = 0; im < 4; im++) {
            const int r = row0 + wm * 64 + im * 16 + g;
            float2 v0 = { acc[im][in][0] + bv.x, acc[im][in][1] + bv.y };
            float2 v1 = { acc[im][in][2] + bv.x, acc[im][in][3] + bv.y };
            *(float2*)(out + (size_t)r * N + col)       = v0;
            *(float2*)(out + (size_t)(r + 8) * N + col) = v1;
        }
    }
}

// ---------------------------------------------------------------------------
// Tensor-core flash attention (TF32), causal + additive padding mask.
// Grid: (T/128, B*NH). Block: 256 threads = 8 warps; warp owns 16 query rows.
// Key tiles of 32. K/V staged in SMEM pre-converted to tf32.
// P round-trips through per-warp SMEM tile to re-fragment for P@V mma.
// ---------------------------------------------------------------------------
#define KT 32
#define QTILE 128
#define KSS 68   // Ks stride:  4 mod 32 -> conflict-free B-frag loads (lane = 4g+tg)
#define VSS 72   // Vs stride:  8 mod 32 -> conflict-free transposed B-frag loads (8tg+g)
#define PSS 36   // Pp stride:  4 mod 32 -> conflict-free A-frag loads

__global__ __launch_bounds__(256, 2)
void attn_tc_kernel(const float* __restrict__ qkv, const float* __restrict__ amask,
                    float* __restrict__ wv)
{
    __shared__ uint32_t Ks[KT * KSS];          // [32][68] tf32
    __shared__ uint32_t Vs[KT * VSS];          // [32][72] tf32
    __shared__ float    Pad[KT];
    __shared__ uint32_t Pp[8][16 * PSS];       // per-warp P tile [16][36] tf32

    const int tid  = threadIdx.x;
    const int warp = tid >> 5;
    const int lane = tid & 31;
    const int g    = lane >> 2;
    const int tg   = lane & 3;
    const int b    = blockIdx.y / NH;
    const int h    = blockIdx.y % NH;
    const int qw   = blockIdx.x * QTILE + warp * 16;   // warp's query rows [qw, qw+16)

    const float* base = qkv + (size_t)b * TT * 3 * CC;

    // Q fragments (tf32), rows g / g+8 of warp tile, 8 k-steps over HD=64
    uint32_t qf[8][4];
    {
        const float* row_lo = base + (size_t)(qw + g)     * 3 * CC + h * HD;
        const float* row_hi = base + (size_t)(qw + g + 8) * 3 * CC + h * HD;
        #pragma unroll
        for (int ks = 0; ks < 8; ks++) {
            qf[ks][0] = f2tf32(row_lo[ks * 8 + tg]);
            qf[ks][1] = f2tf32(row_hi[ks * 8 + tg]);
            qf[ks][2] = f2tf32(row_lo[ks * 8 + tg + 4]);
            qf[ks][3] = f2tf32(row_hi[ks * 8 + tg + 4]);
        }
    }

    float o[8][4];
    #pragma unroll
    for (int nt = 0; nt < 8; nt++)
        #pragma unroll
        for (int r = 0; r < 4; r++) o[nt][r] = 0.0f;
    float m_lo = -INFINITY, m_hi = -INFINITY;
    float l_lo = 0.0f, l_hi = 0.0f;

    const int q_lo = qw + g;
    const int q_hi = qw + g + 8;
    const int ntiles = (blockIdx.x + 1) * (QTILE / KT);

    for (int t = 0; t < ntiles; t++) {
        const int k0 = t * KT;
        __syncthreads();
        // Stage K,V tile (32 rows x 64) converted to tf32. 512 float4 each.
        #pragma unroll
        for (int l2 = 0; l2 < 2; l2++) {
            int i = tid + l2 * 256;
            int r = i >> 4;
            int c = (i & 15) * 4;
            const float* kp = base + (size_t)(k0 + r) * 3 * CC + CC + h * HD + c;
            float4 kv = *(const float4*)kp;
            float4 vv = *(const float4*)(kp + CC);
            uint4 kt4 = { f2tf32(kv.x), f2tf32(kv.y), f2tf32(kv.z), f2tf32(kv.w) };
            uint4 vt4 = { f2tf32(vv.x), f2tf32(vv.y), f2tf32(vv.z), f2tf32(vv.w) };
            *(uint4*)&Ks[r * KSS + c] = kt4;
            *(uint4*)&Vs[r * VSS + c] = vt4;
        }
        if (tid < KT)
            Pad[tid] = (1.0f - amask[b * TT + k0 + tid]) * (-3.402823466e38f);
        __syncthreads();

        // ---- S = Q K^T (warp: 16 x 32) ----
        float s[4][4];
        #pragma unroll
        for (int nt = 0; nt < 4; nt++)
            #pragma unroll
            for (int r = 0; r < 4; r++) s[nt][r] = 0.0f;

        #pragma unroll
        for (int nt = 0; nt < 4; nt++) {
            #pragma unroll
            for (int ks = 0; ks < 8; ks++) {
                uint32_t bf[2];
                bf[0] = Ks[(nt * 8 + g) * KSS + ks * 8 + tg];
                bf[1] = Ks[(nt * 8 + g) * KSS + ks * 8 + tg + 4];
                mma_tf32(s[nt], qf[ks], bf);
            }
        }

        // ---- scale + pad + causal mask, row max ----
        float mt_lo = m_lo, mt_hi = m_hi;
        #pragma unroll
        for (int nt = 0; nt < 4; nt++) {
            const int kk = k0 + nt * 8 + 2 * tg;
            const float pad0 = Pad[nt * 8 + 2 * tg];
            const float pad1 = Pad[nt * 8 + 2 * tg + 1];
            s[nt][0] = (kk     <= q_lo) ? s[nt][0] * ATT_SCALE + pad0 : -INFINITY;
            s[nt][1] = (kk + 1 <= q_lo) ? s[nt][1] * ATT_SCALE + pad1 : -INFINITY;
            s[nt][2] = (kk     <= q_hi) ? s[nt][2] * ATT_SCALE + pad0 : -INFINITY;
            s[nt][3] = (kk + 1 <= q_hi) ? s[nt][3] * ATT_SCALE + pad1 : -INFINITY;
            mt_lo = fmaxf(mt_lo, fmaxf(s[nt][0], s[nt][1]));
            mt_hi = fmaxf(mt_hi, fmaxf(s[nt][2], s[nt][3]));
        }
        mt_lo = fmaxf(mt_lo, __shfl_xor_sync(0xFFFFFFFFu, mt_lo, 1));
        mt_lo = fmaxf(mt_lo, __shfl_xor_sync(0xFFFFFFFFu, mt_lo, 2));
        mt_hi = fmaxf(mt_hi, __shfl_xor_sync(0xFFFFFFFFu, mt_hi, 1));
        mt_hi = fmaxf(mt_hi, __shfl_xor_sync(0xFFFFFFFFu, mt_hi, 2));

        const float alpha_lo = __expf(m_lo - mt_lo);   // 0 on first tile (m=-inf)
        const float alpha_hi = __expf(m_hi - mt_hi);
        m_lo = mt_lo; m_hi = mt_hi;
        l_lo *= alpha_lo; l_hi *= alpha_hi;
        #pragma unroll
        for (int nt = 0; nt < 8; nt++) {
            o[nt][0] *= alpha_lo; o[nt][1] *= alpha_lo;
            o[nt][2] *= alpha_hi; o[nt][3] *= alpha_hi;
        }

        // ---- P = exp(S - m); row sum; store tf32 P to per-warp SMEM ----
        float sl_lo = 0.0f, sl_hi = 0.0f;
        uint32_t* pw = Pp[warp];
        #pragma unroll
        for (int nt = 0; nt < 4; nt++) {
            float p0 = __expf(s[nt][0] - mt_lo);
            float p1 = __expf(s[nt][1] - mt_lo);
            float p2 = __expf(s[nt][2] - mt_hi);
            float p3 = __expf(s[nt][3] - mt_hi);
            sl_lo += p0 + p1;
            sl_hi += p2 + p3;
            uint2 v0 = { f2tf32(p0), f2tf32(p1) };
            uint2 v1 = { f2tf32(p2), f2tf32(p3) };
            *(uint2*)&pw[g       * PSS + nt * 8 + 2 * tg] = v0;
            *(uint2*)&pw[(g + 8) * PSS + nt * 8 + 2 * tg] = v1;
        }
        sl_lo += __shfl_xor_sync(0xFFFFFFFFu, sl_lo, 1);
        sl_lo += __shfl_xor_sync(0xFFFFFFFFu, sl_lo, 2);
        sl_hi += __shfl_xor_sync(0xFFFFFFFFu, sl_hi, 1);
        sl_hi += __shfl_xor_sync(0xFFFFFFFFu, sl_hi, 2);
        l_lo += sl_lo;
        l_hi += sl_hi;
        __syncwarp();

        // ---- O += P @ V ----
        #pragma unroll
        for (int kt2 = 0; kt2 < 4; kt2++) {
            uint32_t af[4];
            af[0] = pw[g       * PSS + kt2 * 8 + tg];
            af[1] = pw[(g + 8) * PSS + kt2 * 8 + tg];
            af[2] = pw[g       * PSS + kt2 * 8 + tg + 4];
            af[3] = pw[(g + 8) * PSS + kt2 * 8 + tg + 4];
            #pragma unroll
            for (int nt = 0; nt < 8; nt++) {
                uint32_t bf[2];
                bf[0] = Vs[(kt2 * 8 + tg)     * VSS + nt * 8 + g];
                bf[1] = Vs[(kt2 * 8 + tg + 4) * VSS + nt * 8 + g];
                mma_tf32(o[nt], af, bf);
            }
        }
        __syncwarp();
    }

    // ---- epilogue: O / l, write to g_wv ----
    const float inv_lo = 1.0f / l_lo;
    const float inv_hi = 1.0f / l_hi;
    float* op = wv + ((size_t)b * TT + qw) * CC + h * HD;
    #pragma unroll
    for (int nt = 0; nt < 8; nt++) {
        const int col = nt * 8 + 2 * tg;
        float2 v0 = { o[nt][0] * inv_lo, o[nt][1] * inv_lo };
        float2 v1 = { o[nt][2] * inv_hi, o[nt][3] * inv_hi };
        *(float2*)(op + (size_t)g       * CC + col) = v0;
        *(float2*)(op + (size_t)(g + 8) * CC + col) = v1;
    }
}

// ---------------------------------------------------------------------------
extern "C" void kernel_launch(void* const* d_in, const int* in_sizes, int n_in,
                              void* d_out, int out_size)
{
    (void)in_sizes; (void)n_in; (void)out_size;
    const float* x      = (const float*)d_in[0];
    const float* amask  = (const float*)d_in[1];
    const float* W_qkv  = (const float*)d_in[2];
    const float* b_qkv  = (const float*)d_in[3];
    const float* W_out  = (const float*)d_in[4];
    const float* b_out  = (const float*)d_in[5];
    float* out = (float*)d_out;

    float* qkv_ptr = nullptr;
    float* wv_ptr  = nullptr;
    cudaGetSymbolAddress((void**)&qkv_ptr, g_qkv);
    cudaGetSymbolAddress((void**)&wv_ptr,  g_wv);

    // 1) QKV projection: (8192 x 1024) @ (1024 x 3072) + b
    {
        dim3 grid(3 * CC / 128, (BB * TT) / 128);
        gemm_tf32_kernel<<<grid, 256>>>(x, W_qkv, b_qkv, qkv_ptr,
                                        BB * TT, 3 * CC, CC);
    }
    // 2) Tensor-core causal flash attention per (b, h)
    {
        dim3 grid(TT / QTILE, BB * NH);
        attn_tc_kernel<<<grid, 256>>>(qkv_ptr, amask, wv_ptr);
    }
    // 3) Output projection: (8192 x 1024) @ (1024 x 1024) + b
    {
        dim3 grid(CC / 128, (BB * TT) / 128);
        gemm_tf32_kernel<<<grid, 256>>>(wv_ptr, W_out, b_out, out,
                                        BB * TT, CC, CC);
    }
}